// round 9
// baseline (speedup 1.0000x reference)
#include <cuda_runtime.h>
#include <cuda_fp16.h>
#include <cstdint>

#define N_NODES 50000
#define D 256
#define E_MAX 800000

// ---------------- scratch (static device globals; no allocation) ----------------
__device__ int   g_deg[N_NODES];
__device__ int   g_rowptr[N_NODES + 1];
__device__ int   g_cursor[N_NODES];
__device__ int   g_eidx[E_MAX];
__device__ __align__(16) float    g_h[(size_t)N_NODES * D];
// A = [mean | self] as fp16 hi/lo, packed 2 halves per u32 along k (512 k -> 256 u32/row)
__device__ __align__(16) uint32_t g_Ahi[(size_t)N_NODES * 256];
__device__ __align__(16) uint32_t g_Alo[(size_t)N_NODES * 256];
// B^T = [Wl;Wr]^T per layer: [layer][n(256)][k2(256)] u32 (2 halves along k)
__device__ __align__(16) uint32_t g_Bt_hi[2 * 256 * 256];
__device__ __align__(16) uint32_t g_Bt_lo[2 * 256 * 256];

// ---------------- small helpers ----------------
__device__ __forceinline__ uint32_t smem_to_u32(const void* p) {
    uint32_t a;
    asm("{ .reg .u64 t; cvta.to.shared.u64 t, %1; cvt.u32.u64 %0, t; }" : "=r"(a) : "l"(p));
    return a;
}

__device__ __forceinline__ uint32_t pack_h2(__half a, __half b) {
    __half2 h = __halves2half2(a, b);
    return *reinterpret_cast<uint32_t*>(&h);
}

// fp16 hi + fp16 residual lo, packed as half2 (low = a)
__device__ __forceinline__ void cvt_hilo2(float a, float b, uint32_t& hi, uint32_t& lo) {
    __half ha = __float2half_rn(a);
    __half hb = __float2half_rn(b);
    __half la = __float2half_rn(a - __half2float(ha));
    __half lb = __float2half_rn(b - __half2float(hb));
    hi = pack_h2(ha, hb);
    lo = pack_h2(la, lb);
}

#define CP_ASYNC16(dst, src, sz) \
    asm volatile("cp.async.cg.shared.global [%0], [%1], 16, %2;" \
        :: "r"(dst), "l"(src), "r"(sz) : "memory")
#define CP_COMMIT() asm volatile("cp.async.commit_group;" ::: "memory")
#define CP_WAIT1() asm volatile("cp.async.wait_group 1;" ::: "memory")
#define CP_WAIT0() asm volatile("cp.async.wait_group 0;" ::: "memory")

#define LDSM_X4(r0, r1, r2, r3, addr) \
    asm volatile("ldmatrix.sync.aligned.m8n8.x4.shared.b16 {%0,%1,%2,%3}, [%4];" \
        : "=r"(r0), "=r"(r1), "=r"(r2), "=r"(r3) : "r"(addr))
#define LDSM_X2(r0, r1, addr) \
    asm volatile("ldmatrix.sync.aligned.m8n8.x2.shared.b16 {%0,%1}, [%2];" \
        : "=r"(r0), "=r"(r1) : "r"(addr))

// fp16 inputs, f32 accumulate (hi*hi term)
__device__ __forceinline__ void mma_f32acc(float* c, const uint32_t* a, uint32_t b0, uint32_t b1) {
    asm volatile(
        "mma.sync.aligned.m16n8k16.row.col.f32.f16.f16.f32 "
        "{%0,%1,%2,%3}, {%4,%5,%6,%7}, {%8,%9}, {%0,%1,%2,%3};\n"
        : "+f"(c[0]), "+f"(c[1]), "+f"(c[2]), "+f"(c[3])
        : "r"(a[0]), "r"(a[1]), "r"(a[2]), "r"(a[3]), "r"(b0), "r"(b1));
}

// fp16 inputs, f16 accumulate (correction terms; values are ~2^-11 relative)
__device__ __forceinline__ void mma_f16acc(uint32_t* c, const uint32_t* a, uint32_t b0, uint32_t b1) {
    asm volatile(
        "mma.sync.aligned.m16n8k16.row.col.f16.f16.f16.f16 "
        "{%0,%1}, {%2,%3,%4,%5}, {%6,%7}, {%0,%1};\n"
        : "+r"(c[0]), "+r"(c[1])
        : "r"(a[0]), "r"(a[1]), "r"(a[2]), "r"(a[3]), "r"(b0), "r"(b1));
}

// ---------------- CSR build ----------------
__global__ void count_kernel(const int* __restrict__ ei, int E) {
    int e = blockIdx.x * blockDim.x + threadIdx.x;
    if (e < E) atomicAdd(&g_deg[ei[E + e]], 1);
}

// single-block full scan: rowptr/cursor from deg; re-zeros deg for the next replay
#define SCAN_PER_T 49
__global__ void scanall_kernel(int E) {
    __shared__ int ssum[1024];
    int t = threadIdx.x;
    int base = t * SCAN_PER_T;
    int s = 0;
#pragma unroll 7
    for (int i = 0; i < SCAN_PER_T; i++) {
        int idx = base + i;
        int v = (idx < N_NODES) ? g_deg[idx] : 0;
        if (idx < N_NODES) g_rowptr[idx] = s;   // local exclusive prefix
        s += v;
    }
    ssum[t] = s;
    __syncthreads();
    for (int off = 1; off < 1024; off <<= 1) {
        int v = (t >= off) ? ssum[t - off] : 0;
        __syncthreads();
        ssum[t] += v;
        __syncthreads();
    }
    int tbase = ssum[t] - s;   // exclusive over threads
#pragma unroll 7
    for (int i = 0; i < SCAN_PER_T; i++) {
        int idx = base + i;
        if (idx < N_NODES) {
            int r = g_rowptr[idx] + tbase;
            g_rowptr[idx] = r;
            g_cursor[idx] = r;
            g_deg[idx]    = 0;   // ready for next replay's count
        }
    }
    if (t == 0) g_rowptr[N_NODES] = E;
}

__global__ void scatter_kernel(const int* __restrict__ ei, int E) {
    int e = blockIdx.x * blockDim.x + threadIdx.x;
    if (e < E) {
        int src = ei[e];
        int dst = ei[E + e];
        int pos = atomicAdd(&g_cursor[dst], 1);
        g_eidx[pos] = src;
    }
}

// ---------------- W -> B^T fp16 hi/lo convert (once) ----------------
__global__ void convert_w_kernel(const float* __restrict__ W1l, const float* __restrict__ W1r,
                                 const float* __restrict__ W2l, const float* __restrict__ W2r) {
    int idx = blockIdx.x * 256 + threadIdx.x;        // 0..131071
    int layer = idx >> 16;
    int n  = (idx >> 8) & 255;
    int k2 = idx & 255;
    int k  = k2 * 2;
    const float* Wl = layer ? W2l : W1l;
    const float* Wr = layer ? W2r : W1r;
    float v0, v1;
    if (k < 256) { v0 = Wl[k * 256 + n]; v1 = Wl[(k + 1) * 256 + n]; }
    else         { v0 = Wr[(k - 256) * 256 + n]; v1 = Wr[(k - 255) * 256 + n]; }
    uint32_t hi, lo;
    cvt_hilo2(v0, v1, hi, lo);
    g_Bt_hi[idx] = hi;
    g_Bt_lo[idx] = lo;
}

// ---------------- mean aggregation + A fp16 hi/lo convert (fused) ----------------
template <bool FROM_H>
__global__ void aggregate_kernel(const float* __restrict__ in_param) {
    const float* __restrict__ in = FROM_H ? (const float*)g_h : in_param;
    int row = blockIdx.x;
    int t   = threadIdx.x;       // 0..127
    int c2  = t * 2;
    int start = g_rowptr[row];
    int end   = g_rowptr[row + 1];
    float a0 = 0.f, a1 = 0.f;
    int e = start;
    for (; e + 4 <= end; e += 4) {
        int s0 = g_eidx[e], s1 = g_eidx[e + 1], s2 = g_eidx[e + 2], s3 = g_eidx[e + 3];
        float2 v0 = *(const float2*)&in[(size_t)s0 * D + c2];
        float2 v1 = *(const float2*)&in[(size_t)s1 * D + c2];
        float2 v2 = *(const float2*)&in[(size_t)s2 * D + c2];
        float2 v3 = *(const float2*)&in[(size_t)s3 * D + c2];
        a0 += (v0.x + v1.x) + (v2.x + v3.x);
        a1 += (v0.y + v1.y) + (v2.y + v3.y);
    }
    for (; e < end; e++) {
        float2 v = *(const float2*)&in[(size_t)g_eidx[e] * D + c2];
        a0 += v.x; a1 += v.y;
    }
    int deg = end - start;
    float scale = (deg > 0) ? 1.f / (float)deg : 0.f;
    uint32_t hi, lo;
    cvt_hilo2(a0 * scale, a1 * scale, hi, lo);
    g_Ahi[(size_t)row * 256 + t] = hi;
    g_Alo[(size_t)row * 256 + t] = lo;
    float2 sv = *(const float2*)&in[(size_t)row * D + c2];
    cvt_hilo2(sv.x, sv.y, hi, lo);
    g_Ahi[(size_t)row * 256 + 128 + t] = hi;
    g_Alo[(size_t)row * 256 + 128 + t] = lo;
}

// ---------------- fp16 mma.sync GEMM, hi/lo comp, f16-acc corrections ----------
// out[M x 256] = A(fp16 hi+lo, [M x 512]) @ B^T(fp16 hi+lo) + bias (opt relu)
// BM=128, BN=128 (grid.y=2), BK=32, 2-stage cp.async, stride-80B smem rows.
#define ROWB 80
#define TILE_BYTES (128 * ROWB)        // 10240 per matrix
#define STAGE_BYTES (4 * TILE_BYTES)   // Ahi, Alo, Bhi, Blo
#define SM_DYN (2 * STAGE_BYTES)       // 81920

template <bool RELU, bool TO_H>
__global__ __launch_bounds__(256, 2) void gemm_f16_kernel(
    int layer, const float* __restrict__ bias, float* __restrict__ out_param)
{
    extern __shared__ char dsm[];
    __shared__ float bias_s[128];

    float* __restrict__ out = TO_H ? (float*)g_h : out_param;
    const uint32_t* __restrict__ BtH = g_Bt_hi + (size_t)layer * 65536;
    const uint32_t* __restrict__ BtL = g_Bt_lo + (size_t)layer * 65536;

    int tid  = threadIdx.x;
    int wid  = tid >> 5;
    int lid  = tid & 31;
    int g    = lid >> 2;
    int tg   = lid & 3;
    int row0 = blockIdx.x * 128;
    int n0   = blockIdx.y * 128;

    int warp_m = (wid & 1) * 64;
    int warp_n = (wid >> 1) * 32;

    if (tid < 128) bias_s[tid] = bias[n0 + tid];

    uint32_t s_base = smem_to_u32(dsm);

    uint32_t a_lane_off = (uint32_t)(((lid & 7) + ((lid >> 3) & 1) * 8) * ROWB + (lid >> 4) * 16);
    uint32_t b_lane_off = (uint32_t)((lid & 7) * ROWB + (((lid & 15) >> 3)) * 16);

    float    acc[4][4][4];   // hi*hi in f32
    uint32_t cor[4][4][2];   // (lo*hi + hi*lo) in f16 pairs
#pragma unroll
    for (int mi = 0; mi < 4; mi++)
#pragma unroll
        for (int ni = 0; ni < 4; ni++) {
#pragma unroll
            for (int r = 0; r < 4; r++) acc[mi][ni][r] = 0.f;
            cor[mi][ni][0] = 0u; cor[mi][ni][1] = 0u;
        }

    int lrow = tid >> 1;
    int lseg = (tid & 1) * 32;
    int gr   = row0 + lrow;
    int a_sz = (gr < N_NODES) ? 16 : 0;
    int gra  = (gr < N_NODES) ? gr : (N_NODES - 1);
    const char* aHs = (const char*)(g_Ahi + (size_t)gra * 256) + lseg;
    const char* aLs = (const char*)(g_Alo + (size_t)gra * 256) + lseg;
    const char* bHs = (const char*)(BtH + (size_t)(n0 + lrow) * 256) + lseg;
    const char* bLs = (const char*)(BtL + (size_t)(n0 + lrow) * 256) + lseg;
    uint32_t dst_row = lrow * ROWB + lseg;

    auto tile_load = [&](int kt, int stage) {
        uint32_t st = s_base + stage * STAGE_BYTES;
        const char* srcA_hi = aHs + kt * 64;
        const char* srcA_lo = aLs + kt * 64;
        const char* srcB_hi = bHs + kt * 64;
        const char* srcB_lo = bLs + kt * 64;
        uint32_t d0 = st + dst_row;
        CP_ASYNC16(d0,                  srcA_hi,      a_sz);
        CP_ASYNC16(d0 + 16,             srcA_hi + 16, a_sz);
        CP_ASYNC16(d0 + TILE_BYTES,     srcA_lo,      a_sz);
        CP_ASYNC16(d0 + TILE_BYTES + 16,srcA_lo + 16, a_sz);
        CP_ASYNC16(d0 + 2 * TILE_BYTES,     srcB_hi,      16);
        CP_ASYNC16(d0 + 2 * TILE_BYTES + 16,srcB_hi + 16, 16);
        CP_ASYNC16(d0 + 3 * TILE_BYTES,     srcB_lo,      16);
        CP_ASYNC16(d0 + 3 * TILE_BYTES + 16,srcB_lo + 16, 16);
    };

    tile_load(0, 0);
    CP_COMMIT();

    for (int kt = 0; kt < 16; kt++) {
        int st = kt & 1;
        if (kt + 1 < 16) { tile_load(kt + 1, st ^ 1); CP_COMMIT(); CP_WAIT1(); }
        else             { CP_WAIT0(); }
        __syncthreads();

        uint32_t sa_h = s_base + st * STAGE_BYTES;
        uint32_t sa_l = sa_h + TILE_BYTES;
        uint32_t sb_h = sa_h + 2 * TILE_BYTES;
        uint32_t sb_l = sa_h + 3 * TILE_BYTES;

#pragma unroll
        for (int ks = 0; ks < 2; ks++) {
            uint32_t koff = ks * 32;
            uint32_t bh[4][2], bl[4][2];
#pragma unroll
            for (int ni = 0; ni < 4; ni++) {
                uint32_t nbase = (uint32_t)((warp_n + ni * 8) * ROWB) + koff;
                LDSM_X2(bh[ni][0], bh[ni][1], sb_h + nbase + b_lane_off);
                LDSM_X2(bl[ni][0], bl[ni][1], sb_l + nbase + b_lane_off);
            }
#pragma unroll
            for (int mi = 0; mi < 4; mi++) {
                uint32_t mbase = (uint32_t)((warp_m + mi * 16) * ROWB) + koff;
                uint32_t ah[4], al[4];
                LDSM_X4(ah[0], ah[1], ah[2], ah[3], sa_h + mbase + a_lane_off);
                LDSM_X4(al[0], al[1], al[2], al[3], sa_l + mbase + a_lane_off);
#pragma unroll
                for (int ni = 0; ni < 4; ni++) mma_f32acc(acc[mi][ni], ah, bh[ni][0], bh[ni][1]);
#pragma unroll
                for (int ni = 0; ni < 4; ni++) mma_f16acc(cor[mi][ni], al, bh[ni][0], bh[ni][1]);
#pragma unroll
                for (int ni = 0; ni < 4; ni++) mma_f16acc(cor[mi][ni], ah, bl[ni][0], bl[ni][1]);
            }
        }
        __syncthreads();
    }

    // epilogue: acc + correction + bias (+relu)
#pragma unroll
    for (int mi = 0; mi < 4; mi++) {
#pragma unroll
        for (int ni = 0; ni < 4; ni++) {
            int lc = warp_n + ni * 8 + tg * 2;
            float bx = bias_s[lc], by = bias_s[lc + 1];
            int gc  = n0 + lc;
            int gr0 = row0 + warp_m + mi * 16 + g;
            int gr1 = gr0 + 8;
            float2 c01 = __half22float2(*reinterpret_cast<const __half2*>(&cor[mi][ni][0]));
            float2 c23 = __half22float2(*reinterpret_cast<const __half2*>(&cor[mi][ni][1]));
            float2 v0, v1;
            v0.x = acc[mi][ni][0] + c01.x + bx; v0.y = acc[mi][ni][1] + c01.y + by;
            v1.x = acc[mi][ni][2] + c23.x + bx; v1.y = acc[mi][ni][3] + c23.y + by;
            if (RELU) {
                v0.x = fmaxf(v0.x, 0.f); v0.y = fmaxf(v0.y, 0.f);
                v1.x = fmaxf(v1.x, 0.f); v1.y = fmaxf(v1.y, 0.f);
            }
            if (gr0 < N_NODES) *(float2*)&out[(size_t)gr0 * D + gc] = v0;
            if (gr1 < N_NODES) *(float2*)&out[(size_t)gr1 * D + gc] = v1;
        }
    }
}

// ---------------- launch ----------------
extern "C" void kernel_launch(void* const* d_in, const int* in_sizes, int n_in,
                              void* d_out, int out_size)
{
    const float* x   = (const float*)d_in[0];
    const int*   ei  = (const int*)d_in[1];     // JAX randint -> int32 (x64 disabled)
    const float* W1l = (const float*)d_in[2];
    const float* b1  = (const float*)d_in[3];
    const float* W1r = (const float*)d_in[4];
    const float* W2l = (const float*)d_in[5];
    const float* b2  = (const float*)d_in[6];
    const float* W2r = (const float*)d_in[7];
    float*       out = (float*)d_out;

    int E = in_sizes[1] / 2;
    if (E > E_MAX) E = E_MAX;

    cudaFuncSetAttribute(gemm_f16_kernel<true, true>,
                         cudaFuncAttributeMaxDynamicSharedMemorySize, SM_DYN);
    cudaFuncSetAttribute(gemm_f16_kernel<false, false>,
                         cudaFuncAttributeMaxDynamicSharedMemorySize, SM_DYN);

    // CSR build + weight conversion (deg starts zero: BSS init + scanall re-zero)
    count_kernel<<<(E + 255) / 256, 256>>>(ei, E);
    scanall_kernel<<<1, 1024>>>(E);
    scatter_kernel<<<(E + 255) / 256, 256>>>(ei, E);
    convert_w_kernel<<<512, 256>>>(W1l, W1r, W2l, W2r);

    dim3 ggrid((N_NODES + 127) / 128, 2);

    // layer 1: h = relu(mean(x) @ W1l + x @ W1r + b1)  -> g_h
    aggregate_kernel<false><<<N_NODES, 128>>>(x);
    gemm_f16_kernel<true, true><<<ggrid, 256, SM_DYN>>>(0, b1, nullptr);

    // layer 2: out = mean(g_h) @ W2l + g_h @ W2r + b2  -> d_out
    aggregate_kernel<true><<<N_NODES, 128>>>(nullptr);
    gemm_f16_kernel<false, false><<<ggrid, 256, SM_DYN>>>(1, b2, out);
}

// round 10
// speedup vs baseline: 1.1953x; 1.1953x over previous
#include <cuda_runtime.h>
#include <cuda_fp16.h>
#include <cstdint>

#define N_NODES 50000
#define D 256
#define E_MAX 800000

// ---------------- scratch (static device globals; no allocation) ----------------
__device__ int   g_deg[N_NODES];
__device__ int   g_rowptr[N_NODES + 1];
__device__ int   g_cursor[N_NODES];
__device__ int   g_eidx[E_MAX];
__device__ __align__(16) float    g_h[(size_t)N_NODES * D];
// A = [mean | self] as fp16 (hi only), packed 2 halves per u32 along k (512 k -> 256 u32/row)
__device__ __align__(16) uint32_t g_Ahi[(size_t)N_NODES * 256];
// B^T = [Wl;Wr]^T per layer: [layer][n(256)][k2(256)] u32 (2 halves along k), hi + residual lo
__device__ __align__(16) uint32_t g_Bt_hi[2 * 256 * 256];
__device__ __align__(16) uint32_t g_Bt_lo[2 * 256 * 256];

// ---------------- small helpers ----------------
__device__ __forceinline__ uint32_t smem_to_u32(const void* p) {
    uint32_t a;
    asm("{ .reg .u64 t; cvta.to.shared.u64 t, %1; cvt.u32.u64 %0, t; }" : "=r"(a) : "l"(p));
    return a;
}

__device__ __forceinline__ uint32_t pack_h2(__half a, __half b) {
    __half2 h = __halves2half2(a, b);
    return *reinterpret_cast<uint32_t*>(&h);
}

__device__ __forceinline__ uint32_t pack_f2h2(float a, float b) {
    return pack_h2(__float2half_rn(a), __float2half_rn(b));
}

// fp16 hi + fp16 residual lo
__device__ __forceinline__ void cvt_hilo2(float a, float b, uint32_t& hi, uint32_t& lo) {
    __half ha = __float2half_rn(a);
    __half hb = __float2half_rn(b);
    __half la = __float2half_rn(a - __half2float(ha));
    __half lb = __float2half_rn(b - __half2float(hb));
    hi = pack_h2(ha, hb);
    lo = pack_h2(la, lb);
}

#define CP_ASYNC16(dst, src, sz) \
    asm volatile("cp.async.cg.shared.global [%0], [%1], 16, %2;" \
        :: "r"(dst), "l"(src), "r"(sz) : "memory")
#define CP_COMMIT() asm volatile("cp.async.commit_group;" ::: "memory")
#define CP_WAIT1() asm volatile("cp.async.wait_group 1;" ::: "memory")
#define CP_WAIT0() asm volatile("cp.async.wait_group 0;" ::: "memory")

#define LDSM_X4(r0, r1, r2, r3, addr) \
    asm volatile("ldmatrix.sync.aligned.m8n8.x4.shared.b16 {%0,%1,%2,%3}, [%4];" \
        : "=r"(r0), "=r"(r1), "=r"(r2), "=r"(r3) : "r"(addr))
#define LDSM_X2(r0, r1, addr) \
    asm volatile("ldmatrix.sync.aligned.m8n8.x2.shared.b16 {%0,%1}, [%2];" \
        : "=r"(r0), "=r"(r1) : "r"(addr))

// fp16 inputs, f32 accumulate
__device__ __forceinline__ void mma_f32acc(float* c, const uint32_t* a, uint32_t b0, uint32_t b1) {
    asm volatile(
        "mma.sync.aligned.m16n8k16.row.col.f32.f16.f16.f32 "
        "{%0,%1,%2,%3}, {%4,%5,%6,%7}, {%8,%9}, {%0,%1,%2,%3};\n"
        : "+f"(c[0]), "+f"(c[1]), "+f"(c[2]), "+f"(c[3])
        : "r"(a[0]), "r"(a[1]), "r"(a[2]), "r"(a[3]), "r"(b0), "r"(b1));
}

// ---------------- CSR build ----------------
__global__ void count_kernel(const int* __restrict__ ei, int E) {
    int e = blockIdx.x * blockDim.x + threadIdx.x;
    if (e < E) atomicAdd(&g_deg[ei[E + e]], 1);
}

// single-block full scan: rowptr/cursor from deg; re-zeros deg for the next replay
#define SCAN_PER_T 49
__global__ void scanall_kernel(int E) {
    __shared__ int ssum[1024];
    int t = threadIdx.x;
    int base = t * SCAN_PER_T;
    int s = 0;
#pragma unroll 7
    for (int i = 0; i < SCAN_PER_T; i++) {
        int idx = base + i;
        int v = (idx < N_NODES) ? g_deg[idx] : 0;
        if (idx < N_NODES) g_rowptr[idx] = s;   // local exclusive prefix
        s += v;
    }
    ssum[t] = s;
    __syncthreads();
    for (int off = 1; off < 1024; off <<= 1) {
        int v = (t >= off) ? ssum[t - off] : 0;
        __syncthreads();
        ssum[t] += v;
        __syncthreads();
    }
    int tbase = ssum[t] - s;   // exclusive over threads
#pragma unroll 7
    for (int i = 0; i < SCAN_PER_T; i++) {
        int idx = base + i;
        if (idx < N_NODES) {
            int r = g_rowptr[idx] + tbase;
            g_rowptr[idx] = r;
            g_cursor[idx] = r;
            g_deg[idx]    = 0;   // ready for next replay's count
        }
    }
    if (t == 0) g_rowptr[N_NODES] = E;
}

__global__ void scatter_kernel(const int* __restrict__ ei, int E) {
    int e = blockIdx.x * blockDim.x + threadIdx.x;
    if (e < E) {
        int src = ei[e];
        int dst = ei[E + e];
        int pos = atomicAdd(&g_cursor[dst], 1);
        g_eidx[pos] = src;
    }
}

// ---------------- W -> B^T fp16 hi/lo convert (once) ----------------
__global__ void convert_w_kernel(const float* __restrict__ W1l, const float* __restrict__ W1r,
                                 const float* __restrict__ W2l, const float* __restrict__ W2r) {
    int idx = blockIdx.x * 256 + threadIdx.x;        // 0..131071
    int layer = idx >> 16;
    int n  = (idx >> 8) & 255;
    int k2 = idx & 255;
    int k  = k2 * 2;
    const float* Wl = layer ? W2l : W1l;
    const float* Wr = layer ? W2r : W1r;
    float v0, v1;
    if (k < 256) { v0 = Wl[k * 256 + n]; v1 = Wl[(k + 1) * 256 + n]; }
    else         { v0 = Wr[(k - 256) * 256 + n]; v1 = Wr[(k - 255) * 256 + n]; }
    uint32_t hi, lo;
    cvt_hilo2(v0, v1, hi, lo);
    g_Bt_hi[idx] = hi;
    g_Bt_lo[idx] = lo;
}

// ---------------- mean aggregation + A fp16 convert (fused, hi only) ----------------
template <bool FROM_H>
__global__ void aggregate_kernel(const float* __restrict__ in_param) {
    const float* __restrict__ in = FROM_H ? (const float*)g_h : in_param;
    int row = blockIdx.x;
    int t   = threadIdx.x;       // 0..127
    int c2  = t * 2;
    int start = g_rowptr[row];
    int end   = g_rowptr[row + 1];
    float a0 = 0.f, a1 = 0.f;
    int e = start;
    for (; e + 4 <= end; e += 4) {
        int s0 = g_eidx[e], s1 = g_eidx[e + 1], s2 = g_eidx[e + 2], s3 = g_eidx[e + 3];
        float2 v0 = *(const float2*)&in[(size_t)s0 * D + c2];
        float2 v1 = *(const float2*)&in[(size_t)s1 * D + c2];
        float2 v2 = *(const float2*)&in[(size_t)s2 * D + c2];
        float2 v3 = *(const float2*)&in[(size_t)s3 * D + c2];
        a0 += (v0.x + v1.x) + (v2.x + v3.x);
        a1 += (v0.y + v1.y) + (v2.y + v3.y);
    }
    for (; e < end; e++) {
        float2 v = *(const float2*)&in[(size_t)g_eidx[e] * D + c2];
        a0 += v.x; a1 += v.y;
    }
    int deg = end - start;
    float scale = (deg > 0) ? 1.f / (float)deg : 0.f;
    g_Ahi[(size_t)row * 256 + t] = pack_f2h2(a0 * scale, a1 * scale);
    float2 sv = *(const float2*)&in[(size_t)row * D + c2];
    g_Ahi[(size_t)row * 256 + 128 + t] = pack_f2h2(sv.x, sv.y);
}

// ---------------- fp16 mma.sync GEMM: A(hi) @ (B_hi + B_lo), 2 terms -----------
// out[M x 256] = A(fp16, [M x 512]) @ B^T(fp16 hi+lo) + bias (opt relu)
// BM=128, BN=128 (grid.y=2), BK=32, 2-stage cp.async, stride-80B smem rows.
#define ROWB 80
#define TILE_BYTES (128 * ROWB)        // 10240 per matrix
#define STAGE_BYTES (3 * TILE_BYTES)   // Ahi, Bhi, Blo
#define SM_DYN (2 * STAGE_BYTES)       // 61440

template <bool RELU, bool TO_H>
__global__ __launch_bounds__(256, 2) void gemm_f16_kernel(
    int layer, const float* __restrict__ bias, float* __restrict__ out_param)
{
    extern __shared__ char dsm[];
    __shared__ float bias_s[128];

    float* __restrict__ out = TO_H ? (float*)g_h : out_param;
    const uint32_t* __restrict__ BtH = g_Bt_hi + (size_t)layer * 65536;
    const uint32_t* __restrict__ BtL = g_Bt_lo + (size_t)layer * 65536;

    int tid  = threadIdx.x;
    int wid  = tid >> 5;
    int lid  = tid & 31;
    int g    = lid >> 2;
    int tg   = lid & 3;
    int row0 = blockIdx.x * 128;
    int n0   = blockIdx.y * 128;

    int warp_m = (wid & 1) * 64;
    int warp_n = (wid >> 1) * 32;

    if (tid < 128) bias_s[tid] = bias[n0 + tid];

    uint32_t s_base = smem_to_u32(dsm);

    uint32_t a_lane_off = (uint32_t)(((lid & 7) + ((lid >> 3) & 1) * 8) * ROWB + (lid >> 4) * 16);
    uint32_t b_lane_off = (uint32_t)((lid & 7) * ROWB + (((lid & 15) >> 3)) * 16);

    float acc[4][4][4];
#pragma unroll
    for (int mi = 0; mi < 4; mi++)
#pragma unroll
        for (int ni = 0; ni < 4; ni++)
#pragma unroll
            for (int r = 0; r < 4; r++) acc[mi][ni][r] = 0.f;

    int lrow = tid >> 1;
    int lseg = (tid & 1) * 32;
    int gr   = row0 + lrow;
    int a_sz = (gr < N_NODES) ? 16 : 0;
    int gra  = (gr < N_NODES) ? gr : (N_NODES - 1);
    const char* aHs = (const char*)(g_Ahi + (size_t)gra * 256) + lseg;
    const char* bHs = (const char*)(BtH + (size_t)(n0 + lrow) * 256) + lseg;
    const char* bLs = (const char*)(BtL + (size_t)(n0 + lrow) * 256) + lseg;
    uint32_t dst_row = lrow * ROWB + lseg;

    auto tile_load = [&](int kt, int stage) {
        uint32_t st = s_base + stage * STAGE_BYTES;
        const char* srcA_hi = aHs + kt * 64;
        const char* srcB_hi = bHs + kt * 64;
        const char* srcB_lo = bLs + kt * 64;
        uint32_t d0 = st + dst_row;
        CP_ASYNC16(d0,                  srcA_hi,      a_sz);
        CP_ASYNC16(d0 + 16,             srcA_hi + 16, a_sz);
        CP_ASYNC16(d0 + TILE_BYTES,     srcB_hi,      16);
        CP_ASYNC16(d0 + TILE_BYTES + 16,srcB_hi + 16, 16);
        CP_ASYNC16(d0 + 2 * TILE_BYTES,     srcB_lo,      16);
        CP_ASYNC16(d0 + 2 * TILE_BYTES + 16,srcB_lo + 16, 16);
    };

    tile_load(0, 0);
    CP_COMMIT();

    for (int kt = 0; kt < 16; kt++) {
        int st = kt & 1;
        if (kt + 1 < 16) { tile_load(kt + 1, st ^ 1); CP_COMMIT(); CP_WAIT1(); }
        else             { CP_WAIT0(); }
        __syncthreads();

        uint32_t sa_h = s_base + st * STAGE_BYTES;
        uint32_t sb_h = sa_h + TILE_BYTES;
        uint32_t sb_l = sa_h + 2 * TILE_BYTES;

#pragma unroll
        for (int ks = 0; ks < 2; ks++) {
            uint32_t koff = ks * 32;
            uint32_t bh[4][2], bl[4][2];
#pragma unroll
            for (int ni = 0; ni < 4; ni++) {
                uint32_t nbase = (uint32_t)((warp_n + ni * 8) * ROWB) + koff;
                LDSM_X2(bh[ni][0], bh[ni][1], sb_h + nbase + b_lane_off);
                LDSM_X2(bl[ni][0], bl[ni][1], sb_l + nbase + b_lane_off);
            }
#pragma unroll
            for (int mi = 0; mi < 4; mi++) {
                uint32_t mbase = (uint32_t)((warp_m + mi * 16) * ROWB) + koff;
                uint32_t ah[4];
                LDSM_X4(ah[0], ah[1], ah[2], ah[3], sa_h + mbase + a_lane_off);
#pragma unroll
                for (int ni = 0; ni < 4; ni++) mma_f32acc(acc[mi][ni], ah, bh[ni][0], bh[ni][1]);
#pragma unroll
                for (int ni = 0; ni < 4; ni++) mma_f32acc(acc[mi][ni], ah, bl[ni][0], bl[ni][1]);
            }
        }
        __syncthreads();
    }

    // epilogue
#pragma unroll
    for (int mi = 0; mi < 4; mi++) {
#pragma unroll
        for (int ni = 0; ni < 4; ni++) {
            int lc = warp_n + ni * 8 + tg * 2;
            float bx = bias_s[lc], by = bias_s[lc + 1];
            int gc  = n0 + lc;
            int gr0 = row0 + warp_m + mi * 16 + g;
            int gr1 = gr0 + 8;
            float2 v0, v1;
            v0.x = acc[mi][ni][0] + bx; v0.y = acc[mi][ni][1] + by;
            v1.x = acc[mi][ni][2] + bx; v1.y = acc[mi][ni][3] + by;
            if (RELU) {
                v0.x = fmaxf(v0.x, 0.f); v0.y = fmaxf(v0.y, 0.f);
                v1.x = fmaxf(v1.x, 0.f); v1.y = fmaxf(v1.y, 0.f);
            }
            if (gr0 < N_NODES) *(float2*)&out[(size_t)gr0 * D + gc] = v0;
            if (gr1 < N_NODES) *(float2*)&out[(size_t)gr1 * D + gc] = v1;
        }
    }
}

// ---------------- launch ----------------
extern "C" void kernel_launch(void* const* d_in, const int* in_sizes, int n_in,
                              void* d_out, int out_size)
{
    const float* x   = (const float*)d_in[0];
    const int*   ei  = (const int*)d_in[1];     // JAX randint -> int32 (x64 disabled)
    const float* W1l = (const float*)d_in[2];
    const float* b1  = (const float*)d_in[3];
    const float* W1r = (const float*)d_in[4];
    const float* W2l = (const float*)d_in[5];
    const float* b2  = (const float*)d_in[6];
    const float* W2r = (const float*)d_in[7];
    float*       out = (float*)d_out;

    int E = in_sizes[1] / 2;
    if (E > E_MAX) E = E_MAX;

    cudaFuncSetAttribute(gemm_f16_kernel<true, true>,
                         cudaFuncAttributeMaxDynamicSharedMemorySize, SM_DYN);
    cudaFuncSetAttribute(gemm_f16_kernel<false, false>,
                         cudaFuncAttributeMaxDynamicSharedMemorySize, SM_DYN);

    // CSR build + weight conversion (deg starts zero: BSS init + scanall re-zero)
    count_kernel<<<(E + 255) / 256, 256>>>(ei, E);
    scanall_kernel<<<1, 1024>>>(E);
    scatter_kernel<<<(E + 255) / 256, 256>>>(ei, E);
    convert_w_kernel<<<512, 256>>>(W1l, W1r, W2l, W2r);

    dim3 ggrid((N_NODES + 127) / 128, 2);

    // layer 1: h = relu(mean(x) @ W1l + x @ W1r + b1)  -> g_h
    aggregate_kernel<false><<<N_NODES, 128>>>(x);
    gemm_f16_kernel<true, true><<<ggrid, 256, SM_DYN>>>(0, b1, nullptr);

    // layer 2: out = mean(g_h) @ W2l + g_h @ W2r + b2  -> d_out
    aggregate_kernel<true><<<N_NODES, 128>>>(nullptr);
    gemm_f16_kernel<false, false><<<ggrid, 256, SM_DYN>>>(1, b2, out);
}